// round 10
// baseline (speedup 1.0000x reference)
#include <cuda_runtime.h>
#include <cuda_bf16.h>
#include <cstdint>

#define LL 512
#define IN_DIM 256
#define DM 32      // dim_msa (contraction dims c and d)
#define PD 64      // pairwise dim
#define CP 2048    // DM*PD
#define IPB 4      // i's per CTA in k_mma
#define NT_T 3     // tensor-part nt tiles (p 0..23)
#define NT_F 5     // fma-part nt tiles (p 24..63)

// ---------------------------------------------------------------------------
// Global scratch.
//   g_Af_*[ ((mt*2+ks)*32 + lane)*4 + reg ]   mt=j>>4, ks=c>>4
//   g_Bf_*[ i*1024 + ((nt*2+ks)*32 + lane)*2 + reg ]  (only nt<3 written/read)
//   g_T   [ i*2048 + c*64 + p ]  fp32 (fma part reads p>=24)
//   g_xT  [ d*512 + i ]          fp32
// ---------------------------------------------------------------------------
__device__ __align__(16) unsigned g_Af_hi[8192];
__device__ __align__(16) unsigned g_Af_lo[8192];
__device__ __align__(16) unsigned g_Bf_hi[512 * 1024];
__device__ __align__(16) unsigned g_Bf_lo[512 * 1024];
__device__ __align__(16) float    g_T[(size_t)LL * CP];
__device__ float g_xT[DM * LL];

__device__ __forceinline__ unsigned pack_bf(__nv_bfloat16 lo16, __nv_bfloat16 hi16) {
    return (unsigned)__bfloat16_as_ushort(lo16) |
           ((unsigned)__bfloat16_as_ushort(hi16) << 16);
}
__device__ __forceinline__ void split_bf(float f, __nv_bfloat16& h, __nv_bfloat16& l) {
    h = __float2bfloat16(f);
    l = __float2bfloat16(f - __bfloat162float(h));
}
__device__ __forceinline__ uint32_t smem_u32(const void* p) {
    uint32_t a;
    asm("{ .reg .u64 t; cvta.to.shared.u64 t, %1; cvt.u32.u64 %0, t; }"
        : "=r"(a) : "l"(p));
    return a;
}
__device__ __forceinline__ void cp_async16(uint32_t dst, const void* src) {
    asm volatile("cp.async.cg.shared.global [%0], [%1], 16;"
                 :: "r"(dst), "l"(src) : "memory");
}
__device__ __forceinline__ void cp_commit() {
    asm volatile("cp.async.commit_group;" ::: "memory");
}
template <int N>
__device__ __forceinline__ void cp_wait() {
    asm volatile("cp.async.wait_group %0;" :: "n"(N) : "memory");
}

// ---------------------------------------------------------------------------
// Fused kernel: per CTA (cp-tile bx, i-tile by):
//   phase 1: compute x[i-tile][32d] from seq @ W1^T + b1 (redundant per bx)
//   phase 2: proj2 body -> g_T fp32 + B-fragments (nt<3)
//   bx==0 CTAs additionally emit g_xT and A-fragments.
// ---------------------------------------------------------------------------
#define W1PAD 260
__global__ void __launch_bounds__(256) k_proj(const float* __restrict__ seq,
                                              const float* __restrict__ W1,
                                              const float* __restrict__ b1,
                                              const float* __restrict__ W2) {
    __shared__ __align__(16) float sbuf[DM * W1PAD];  // phase1 W1s[d][k] / phase2 ws[k][cp]
    __shared__ float xs[DM][33];                      // [d][i_local], pad 33: conflict-free
    const int tid = threadIdx.x;
    const int cp0 = blockIdx.x * 256;
    const int i0  = blockIdx.y * 32;

    // ---- phase 1: W1 -> sbuf as [d][W1PAD] ----
    #pragma unroll
    for (int t = 0; t < 8; ++t) {
        int idx4 = t * 256 + tid;
        int d = idx4 >> 6, k4 = idx4 & 63;
        *(float4*)&sbuf[d * W1PAD + k4 * 4] = ((const float4*)W1)[idx4];
    }
    __syncthreads();

    const int w = tid >> 5, d = tid & 31;   // warp w owns rows i0+w*4 .. +3, lane=d
    float xv[4];
    {
        const float4* s0 = (const float4*)(seq + (i0 + w * 4 + 0) * IN_DIM);
        const float4* s1 = (const float4*)(seq + (i0 + w * 4 + 1) * IN_DIM);
        const float4* s2 = (const float4*)(seq + (i0 + w * 4 + 2) * IN_DIM);
        const float4* s3 = (const float4*)(seq + (i0 + w * 4 + 3) * IN_DIM);
        float a0 = 0.f, a1 = 0.f, a2 = 0.f, a3 = 0.f;
        #pragma unroll 8
        for (int k4 = 0; k4 < 64; ++k4) {
            float4 wv = *(const float4*)&sbuf[d * W1PAD + k4 * 4];
            float4 q0 = __ldg(s0 + k4);
            float4 q1 = __ldg(s1 + k4);
            float4 q2 = __ldg(s2 + k4);
            float4 q3 = __ldg(s3 + k4);
            a0 = fmaf(q0.x, wv.x, fmaf(q0.y, wv.y, fmaf(q0.z, wv.z, fmaf(q0.w, wv.w, a0))));
            a1 = fmaf(q1.x, wv.x, fmaf(q1.y, wv.y, fmaf(q1.z, wv.z, fmaf(q1.w, wv.w, a1))));
            a2 = fmaf(q2.x, wv.x, fmaf(q2.y, wv.y, fmaf(q2.z, wv.z, fmaf(q2.w, wv.w, a2))));
            a3 = fmaf(q3.x, wv.x, fmaf(q3.y, wv.y, fmaf(q3.z, wv.z, fmaf(q3.w, wv.w, a3))));
        }
        float bv = __ldg(b1 + d);
        xv[0] = a0 + bv; xv[1] = a1 + bv; xv[2] = a2 + bv; xv[3] = a3 + bv;
    }
    #pragma unroll
    for (int r = 0; r < 4; ++r) xs[d][w * 4 + r] = xv[r];

    // bx==0: emit g_xT + A-fragments
    if (blockIdx.x == 0) {
        #pragma unroll
        for (int r = 0; r < 4; ++r) {
            const int j = i0 + w * 4 + r;
            g_xT[d * LL + j] = xv[r];
            float pv = __shfl_xor_sync(0xffffffffu, xv[r], 1);
            if (!(d & 1)) {
                __nv_bfloat16 h0, l0, h1, l1;
                split_bf(xv[r], h0, l0);
                split_bf(pv,    h1, l1);
                const int mt = j >> 4, jr = j & 15;
                const int ks = d >> 4, kc = d & 15;
                const int lane = (jr & 7) * 4 + ((kc >> 1) & 3);
                const int reg  = (jr >> 3) | ((kc >> 3) << 1);
                const int idx  = ((mt * 2 + ks) * 32 + lane) * 4 + reg;
                g_Af_hi[idx] = pack_bf(h0, h1);
                g_Af_lo[idx] = pack_bf(l0, l1);
            }
        }
    }
    __syncthreads();

    // ---- phase 2: ws = W2 slice -> sbuf as [k][cp_local] ----
    #pragma unroll
    for (int t = 0; t < 32; ++t) {
        int idx = t * 256 + tid;
        int cpl = idx >> 5, k = idx & 31;
        int cp = cp0 + cpl;
        sbuf[k * 256 + cpl] = W2[(cp & 63) * 1024 + (cp >> 6) * 32 + k];
    }
    __syncthreads();

    const int cg = tid & 31;
    const int ig = tid >> 5;
    float acc[4][8];
    #pragma unroll
    for (int a = 0; a < 4; ++a)
        #pragma unroll
        for (int b = 0; b < 8; ++b) acc[a][b] = 0.f;

    #pragma unroll 4
    for (int k = 0; k < DM; ++k) {
        float xr[4];
        #pragma unroll
        for (int a = 0; a < 4; ++a) xr[a] = xs[k][ig * 4 + a];
        float4 wa = *(const float4*)&sbuf[k * 256 + cg * 8];
        float4 wb = *(const float4*)&sbuf[k * 256 + cg * 8 + 4];
        float wv[8] = {wa.x, wa.y, wa.z, wa.w, wb.x, wb.y, wb.z, wb.w};
        #pragma unroll
        for (int a = 0; a < 4; ++a)
            #pragma unroll
            for (int b = 0; b < 8; ++b)
                acc[a][b] = fmaf(xr[a], wv[b], acc[a][b]);
    }

    // g_T fp32 (full)
    #pragma unroll
    for (int a = 0; a < 4; ++a) {
        float* dst = &g_T[(size_t)(i0 + ig * 4 + a) * CP + cp0 + cg * 8];
        *(float4*)(dst)     = make_float4(acc[a][0], acc[a][1], acc[a][2], acc[a][3]);
        *(float4*)(dst + 4) = make_float4(acc[a][4], acc[a][5], acc[a][6], acc[a][7]);
    }

    // B-fragments, only nt < 3 (tensor part covers p<24)
    const int cbase = blockIdx.x * 4 + (cg >> 3);
    const bool even = ((cg >> 3) & 1) == 0;
    const int nt = cg & 7;
    #pragma unroll
    for (int a = 0; a < 4; ++a) {
        const int i = i0 + ig * 4 + a;
        unsigned* bh = g_Bf_hi + i * 1024;
        unsigned* bl = g_Bf_lo + i * 1024;
        #pragma unroll
        for (int b = 0; b < 8; ++b) {
            float v  = acc[a][b];
            float pv = __shfl_xor_sync(0xffffffffu, v, 8);
            if (even && nt < NT_T) {
                __nv_bfloat16 h0, l0, h1, l1;
                split_bf(v,  h0, l0);
                split_bf(pv, h1, l1);
                const int ks = cbase >> 4, kc = cbase & 15;
                const int lanef = b * 4 + ((kc >> 1) & 3);
                const int reg   = kc >> 3;
                const int bidx  = ((nt * 2 + ks) * 32 + lanef) * 2 + reg;
                bh[bidx] = pack_bf(h0, h1);
                bl[bidx] = pack_bf(l0, l1);
            }
        }
    }
}

// ---------------------------------------------------------------------------
// Hybrid k_mma: out[i][j][p] = b2[p] + sum_c x[j][c]*T[i][c][p]
//   tensor pipe: p 0..23 (3-term bf16 HMMA, fragments)
//   fp32 pipe:   p 24..63 (exact FFMA2 from smem-staged x and T)
// grid (2 jt, 128 ib), 256 threads, 2 CTAs/SM. smem = 48KB exactly.
// ---------------------------------------------------------------------------
#define MMA_BF16(C, A, B)                                                      \
    asm volatile("mma.sync.aligned.m16n8k16.row.col.f32.bf16.bf16.f32 "        \
                 "{%0,%1,%2,%3}, {%4,%5,%6,%7}, {%8,%9}, {%0,%1,%2,%3};"       \
                 : "+f"((C)[0]), "+f"((C)[1]), "+f"((C)[2]), "+f"((C)[3])      \
                 : "r"((A).x), "r"((A).y), "r"((A).z), "r"((A).w),             \
                   "r"((B).x), "r"((B).y))

__global__ void __launch_bounds__(256, 2) k_mma(const float* __restrict__ b2,
                                                float* __restrict__ out) {
    __shared__ __align__(16) float    xjs[DM][256];       // 32 KB  [c][j_local]
    __shared__ __align__(16) unsigned smBf[2][768];       //  6 KB  [buf][hi|lo]
    __shared__ __align__(16) float    smT[2][DM][40];     // 10 KB  [buf][c][p-24]

    const int tid = threadIdx.x;
    const int w = tid >> 5, l = tid & 31;
    const int gid = l >> 2, q = l & 3;
    const int jt = blockIdx.x;
    const int ibase = blockIdx.y * IPB;

    // A fragments (tensor part), once per CTA
    uint4 Ah[2][2], Al[2][2];   // [ks][m]
    #pragma unroll
    for (int ks = 0; ks < 2; ++ks)
        #pragma unroll
        for (int m = 0; m < 2; ++m) {
            const int mt  = jt * 16 + w * 2 + m;
            const int off = ((mt * 2 + ks) * 32 + l) * 4;
            Ah[ks][m] = *(const uint4*)(g_Af_hi + off);
            Al[ks][m] = *(const uint4*)(g_Af_lo + off);
        }

    const uint32_t xjs_b = smem_u32(&xjs[0][0]);
    const uint32_t bf_b  = smem_u32(&smBf[0][0]);
    const uint32_t smT_b = smem_u32(&smT[0][0][0]);

    // xjs: x[j0..j0+255][c] from g_xT (2048 x 16B)
    #pragma unroll
    for (int t8 = 0; t8 < 8; ++t8) {
        int o = tid + 256 * t8;
        int c = o >> 6, p4 = o & 63;
        cp_async16(xjs_b + o * 16, (const uint4*)(g_xT + c * LL + jt * 256) + p4);
    }
    // stage loader: Bf (192 ops) + T subset (320 ops)
    auto load_stage = [&](int i, int buf) {
        #pragma unroll
        for (int t2 = 0; t2 < 2; ++t2) {
            int o = tid + 256 * t2;
            if (o < 96)
                cp_async16(bf_b + buf * 3072 + o * 16, (const uint4*)(g_Bf_hi + i * 1024) + o);
            else if (o < 192)
                cp_async16(bf_b + buf * 3072 + o * 16, (const uint4*)(g_Bf_lo + i * 1024) + (o - 96));
            else {
                int r = o - 192;               // 0..319
                int c = r / 10, part = r % 10;
                cp_async16(smT_b + buf * 5120 + c * 160 + part * 16,
                           (const float4*)(g_T + (size_t)i * CP + c * PD + 24) + part);
            }
        }
    };

    load_stage(ibase, 0);
    cp_commit();

    for (int t = 0; t < IPB; ++t) {
        if (t > 0) __syncthreads();
        if (t + 1 < IPB) {
            load_stage(ibase + t + 1, (t + 1) & 1);
            cp_commit();
            cp_wait<1>();
        } else {
            cp_wait<0>();
        }
        __syncthreads();

        const unsigned* bf = smBf[t & 1];
        const float (*Tt)[40] = smT[t & 1];
        float* rowbase = out + ((size_t)(ibase + t) * LL + jt * 256 + w * 32) * PD;

        // ---- tensor part: nt 0..2 ----
        float acc_t[2][NT_T][4];
        #pragma unroll
        for (int m = 0; m < 2; ++m)
            #pragma unroll
            for (int n = 0; n < NT_T; ++n)
                #pragma unroll
                for (int e = 0; e < 4; ++e) acc_t[m][n][e] = 0.f;
        #pragma unroll
        for (int n = 0; n < NT_T; ++n)
            #pragma unroll
            for (int ks = 0; ks < 2; ++ks) {
                const int off = ((n * 2 + ks) * 32 + l) * 2;
                uint2 Bh = *(const uint2*)(bf + off);
                uint2 Bl = *(const uint2*)(bf + 384 + off);
                #pragma unroll
                for (int m = 0; m < 2; ++m) {
                    MMA_BF16(acc_t[m][n], Ah[ks][m], Bh);
                    MMA_BF16(acc_t[m][n], Ah[ks][m], Bl);
                    MMA_BF16(acc_t[m][n], Al[ks][m], Bh);
                }
            }

        // ---- fp32 part: p 24..63, rows {w*32+gid+8r} ----
        unsigned long long accf[4][NT_F];
        #pragma unroll
        for (int n = 0; n < NT_F; ++n) {
            float2 bb = __ldg((const float2*)(b2 + 24 + n * 8 + q * 2));
            unsigned long long bv;
            asm("mov.b64 %0, {%1, %2};" : "=l"(bv) : "f"(bb.x), "f"(bb.y));
            #pragma unroll
            for (int r = 0; r < 4; ++r) accf[r][n] = bv;
        }
        #pragma unroll 4
        for (int c = 0; c < DM; ++c) {
            unsigned long long x2[4];
            #pragma unroll
            for (int r = 0; r < 4; ++r) {
                float xv = xjs[c][w * 32 + gid + r * 8];
                asm("mov.b64 %0, {%1, %1};" : "=l"(x2[r]) : "f"(xv));
            }
            #pragma unroll
            for (int n = 0; n < NT_F; ++n) {
                unsigned long long tv =
                    *(const unsigned long long*)&Tt[c][n * 8 + q * 2];
                #pragma unroll
                for (int r = 0; r < 4; ++r)
                    asm("fma.rn.f32x2 %0, %1, %2, %0;"
                        : "+l"(accf[r][n]) : "l"(x2[r]), "l"(tv));
            }
        }

        // ---- epilogue ----
        #pragma unroll
        for (int m = 0; m < 2; ++m)
            #pragma unroll
            for (int n = 0; n < NT_T; ++n) {
                float2 bb = __ldg((const float2*)(b2 + n * 8 + 2 * q));
                float* d0 = rowbase + (m * 16 + gid) * PD + n * 8 + 2 * q;
                *(float2*)d0 =
                    make_float2(acc_t[m][n][0] + bb.x, acc_t[m][n][1] + bb.y);
                *(float2*)(d0 + 8 * PD) =
                    make_float2(acc_t[m][n][2] + bb.x, acc_t[m][n][3] + bb.y);
            }
        #pragma unroll
        for (int r = 0; r < 4; ++r)
            #pragma unroll
            for (int n = 0; n < NT_F; ++n) {
                float* d0 = rowbase + (gid + r * 8) * PD + 24 + n * 8 + q * 2;
                *(unsigned long long*)d0 = accf[r][n];
            }
    }
}

// ---------------------------------------------------------------------------
extern "C" void kernel_launch(void* const* d_in, const int* in_sizes, int n_in,
                              void* d_out, int out_size) {
    const float* seq = (const float*)d_in[0];
    const float* W1  = (const float*)d_in[1];
    const float* b1  = (const float*)d_in[2];
    const float* W2  = (const float*)d_in[3];
    const float* b2  = (const float*)d_in[4];
    float* out = (float*)d_out;

    k_proj<<<dim3(8, 16), 256>>>(seq, W1, b1, W2);
    k_mma<<<dim3(2, LL / IPB), 256>>>(b2, out);
}

// round 11
// speedup vs baseline: 1.5830x; 1.5830x over previous
#include <cuda_runtime.h>
#include <cuda_bf16.h>
#include <cstdint>

#define LL 512
#define IN_DIM 256
#define DM 32      // dim_msa (contraction dims c and d)
#define PD 64      // pairwise dim
#define CP 2048    // DM*PD
#define IPB 4      // i's per CTA in k_mma

// ---------------------------------------------------------------------------
// Global scratch. Fragment layouts:
//   g_Af_*[ ((mt*2+ks)*32 + lane)*4 + reg ]            mt=j>>4 (32), ks=c>>4 (2)
//   g_Bf_*[ i*1024 + (nt*32 + lane)*4 + ks*2 + reg ]   nt=p>>3 (8)  <- 16B/(nt,lane)
// ---------------------------------------------------------------------------
__device__ __align__(16) unsigned g_Af_hi[8192];
__device__ __align__(16) unsigned g_Af_lo[8192];
__device__ __align__(16) unsigned g_Bf_hi[512 * 1024];
__device__ __align__(16) unsigned g_Bf_lo[512 * 1024];
__device__ float g_xT[DM * LL];          // x transposed: [d][i]

__device__ __forceinline__ unsigned pack_bf(__nv_bfloat16 lo16, __nv_bfloat16 hi16) {
    return (unsigned)__bfloat16_as_ushort(lo16) |
           ((unsigned)__bfloat16_as_ushort(hi16) << 16);
}
__device__ __forceinline__ void split_bf(float f, __nv_bfloat16& h, __nv_bfloat16& l) {
    h = __float2bfloat16(f);
    l = __float2bfloat16(f - __bfloat162float(h));
}
__device__ __forceinline__ uint32_t smem_u32(const void* p) {
    uint32_t a;
    asm("{ .reg .u64 t; cvta.to.shared.u64 t, %1; cvt.u32.u64 %0, t; }"
        : "=r"(a) : "l"(p));
    return a;
}
__device__ __forceinline__ void cp_async16(uint32_t dst, const void* src) {
    asm volatile("cp.async.cg.shared.global [%0], [%1], 16;"
                 :: "r"(dst), "l"(src) : "memory");
}
__device__ __forceinline__ void cp_commit() {
    asm volatile("cp.async.commit_group;" ::: "memory");
}
template <int N>
__device__ __forceinline__ void cp_wait() {
    asm volatile("cp.async.wait_group %0;" :: "n"(N) : "memory");
}

// ---------------------------------------------------------------------------
// Kernel A (R8, measured 5.9us): x = seq @ W1^T + b1; emits g_xT + A-frags.
// grid 128 x block 128; CTA = 4 rows; cross-warp reduce over k-chunks.
// ---------------------------------------------------------------------------
#define W1PAD 260
__global__ void __launch_bounds__(128) k_proj1(const float* __restrict__ seq,
                                               const float* __restrict__ W1,
                                               const float* __restrict__ b1) {
    __shared__ __align__(16) float W1s[DM][W1PAD];
    __shared__ __align__(16) float seqs[4][IN_DIM];
    __shared__ __align__(16) float red[4][4][32];
    const int tid = threadIdx.x;
    const int i0 = blockIdx.x * 4;

    #pragma unroll
    for (int t = 0; t < 16; ++t) {
        int idx4 = t * 128 + tid;
        int d = idx4 >> 6, k4 = idx4 & 63;
        *(float4*)&W1s[d][k4 * 4] = ((const float4*)W1)[idx4];
    }
    #pragma unroll
    for (int t = 0; t < 2; ++t) {
        int idx4 = t * 128 + tid;
        int r = idx4 >> 6, k4 = idx4 & 63;
        *(float4*)&seqs[r][k4 * 4] = ((const float4*)seq)[(i0 + r) * 64 + k4];
    }
    __syncthreads();

    const int d  = tid & 31;
    const int kc = tid >> 5;
    float acc[4][4];
    #pragma unroll
    for (int r = 0; r < 4; ++r)
        #pragma unroll
        for (int e = 0; e < 4; ++e) acc[r][e] = 0.f;

    #pragma unroll
    for (int i4 = 0; i4 < 16; ++i4) {
        float4 wv = *(const float4*)&W1s[d][kc * 64 + i4 * 4];
        #pragma unroll
        for (int r = 0; r < 4; ++r) {
            float4 s = *(const float4*)&seqs[r][kc * 64 + i4 * 4];
            acc[r][0] = fmaf(s.x, wv.x, acc[r][0]);
            acc[r][1] = fmaf(s.y, wv.y, acc[r][1]);
            acc[r][2] = fmaf(s.z, wv.z, acc[r][2]);
            acc[r][3] = fmaf(s.w, wv.w, acc[r][3]);
        }
    }
    #pragma unroll
    for (int r = 0; r < 4; ++r)
        red[r][kc][d] = (acc[r][0] + acc[r][1]) + (acc[r][2] + acc[r][3]);
    __syncthreads();

    const int rr = tid >> 5, dd = tid & 31;
    float a = (red[rr][0][dd] + red[rr][1][dd]) +
              (red[rr][2][dd] + red[rr][3][dd]) + b1[dd];

    const int j = i0 + rr;
    g_xT[dd * LL + j] = a;

    float pv = __shfl_xor_sync(0xffffffffu, a, 1);
    if (!(dd & 1)) {
        __nv_bfloat16 h0, l0, h1, l1;
        split_bf(a,  h0, l0);
        split_bf(pv, h1, l1);
        const int mt = j >> 4, jr = j & 15;
        const int ks = dd >> 4, kcx = dd & 15;
        const int lane = (jr & 7) * 4 + ((kcx >> 1) & 3);
        const int reg  = (jr >> 3) | ((kcx >> 3) << 1);
        const int idx  = ((mt * 2 + ks) * 32 + lane) * 4 + reg;
        g_Af_hi[idx] = pack_bf(h0, h1);
        g_Af_lo[idx] = pack_bf(l0, l1);
    }
}

// ---------------------------------------------------------------------------
// Kernel B: T = x @ W2-slice; emits B-fragments ONLY (new 16B layout).
// grid (8 cp-tiles, 16 i-tiles), block 256.
// ---------------------------------------------------------------------------
__global__ void __launch_bounds__(256) k_proj2(const float* __restrict__ W2) {
    __shared__ __align__(16) float ws[DM][256];
    __shared__ __align__(16) float xs[DM][32];
    const int tid = threadIdx.x;
    const int cp0 = blockIdx.x * 256;
    const int i0  = blockIdx.y * 32;

    #pragma unroll
    for (int t = 0; t < 32; ++t) {
        int idx = t * 256 + tid;
        int cpl = idx >> 5, k = idx & 31;
        int cp = cp0 + cpl;
        ws[k][cpl] = W2[(cp & 63) * 1024 + (cp >> 6) * 32 + k];
    }
    #pragma unroll
    for (int t = 0; t < 4; ++t) {
        int idx = t * 256 + tid;
        int k = idx >> 5, il = idx & 31;
        xs[k][il] = g_xT[k * LL + i0 + il];
    }
    __syncthreads();

    const int cg = tid & 31;
    const int ig = tid >> 5;
    float acc[4][8];
    #pragma unroll
    for (int a = 0; a < 4; ++a)
        #pragma unroll
        for (int b = 0; b < 8; ++b) acc[a][b] = 0.f;

    #pragma unroll 4
    for (int k = 0; k < DM; ++k) {
        float4 xv = *(const float4*)&xs[k][ig * 4];
        float4 wa = *(const float4*)&ws[k][cg * 8];
        float4 wb = *(const float4*)&ws[k][cg * 8 + 4];
        float xr[4] = {xv.x, xv.y, xv.z, xv.w};
        float wv[8] = {wa.x, wa.y, wa.z, wa.w, wb.x, wb.y, wb.z, wb.w};
        #pragma unroll
        for (int a = 0; a < 4; ++a)
            #pragma unroll
            for (int b = 0; b < 8; ++b)
                acc[a][b] = fmaf(xr[a], wv[b], acc[a][b]);
    }

    // B-fragment emit, new layout: (nt*32+lane)*4 + ks*2 + reg
    const int cbase = blockIdx.x * 4 + (cg >> 3);   // this thread's c
    const bool even = ((cg >> 3) & 1) == 0;
    const int nt = cg & 7;                           // p>>3
    #pragma unroll
    for (int a = 0; a < 4; ++a) {
        const int i = i0 + ig * 4 + a;
        unsigned* bh = g_Bf_hi + i * 1024;
        unsigned* bl = g_Bf_lo + i * 1024;
        #pragma unroll
        for (int b = 0; b < 8; ++b) {
            float v  = acc[a][b];
            float pv = __shfl_xor_sync(0xffffffffu, v, 8);
            if (even) {
                __nv_bfloat16 h0, l0, h1, l1;
                split_bf(v,  h0, l0);   // c (even)
                split_bf(pv, h1, l1);   // c+1
                const int ks = cbase >> 4, kc = cbase & 15;
                const int lanef = b * 4 + ((kc >> 1) & 3);
                const int reg   = kc >> 3;
                const int bidx  = (nt * 32 + lanef) * 4 + ks * 2 + reg;
                bh[bidx] = pack_bf(h0, h1);
                bl[bidx] = pack_bf(l0, l1);
            }
        }
    }
}

// ---------------------------------------------------------------------------
// Kernel C (pure HMMA): out[i][j][p] = b2[p] + sum_c x[j][c]*T[i][c][p]
// grid (2 jt, 128 ib), block 256 (8 warps x 32j x 64p), 2 CTAs/SM, IPB=4.
// B-frags: one LDS.128 per (nt, hi/lo). acc in nt-halves (32 regs live).
// ---------------------------------------------------------------------------
#define MMA_BF16(C, A, B)                                                      \
    asm volatile("mma.sync.aligned.m16n8k16.row.col.f32.bf16.bf16.f32 "        \
                 "{%0,%1,%2,%3}, {%4,%5,%6,%7}, {%8,%9}, {%0,%1,%2,%3};"       \
                 : "+f"((C)[0]), "+f"((C)[1]), "+f"((C)[2]), "+f"((C)[3])      \
                 : "r"((A).x), "r"((A).y), "r"((A).z), "r"((A).w),             \
                   "r"((B).x), "r"((B).y))

__global__ void __launch_bounds__(256, 2) k_mma(const float* __restrict__ b2,
                                                float* __restrict__ out) {
    __shared__ __align__(16) unsigned smBf[2][2048];   // [buf][hi 1024 | lo 1024]

    const int tid = threadIdx.x;
    const int w = tid >> 5, l = tid & 31;
    const int gid = l >> 2, q = l & 3;
    const int jt = blockIdx.x;
    const int ibase = blockIdx.y * IPB;

    // A fragments once per CTA (i-independent)
    uint4 Ah[2][2], Al[2][2];   // [ks][m]
    #pragma unroll
    for (int ks = 0; ks < 2; ++ks)
        #pragma unroll
        for (int m = 0; m < 2; ++m) {
            const int mt  = jt * 16 + w * 2 + m;
            const int off = ((mt * 2 + ks) * 32 + l) * 4;
            Ah[ks][m] = *(const uint4*)(g_Af_hi + off);
            Al[ks][m] = *(const uint4*)(g_Af_lo + off);
        }

    const uint32_t smb = smem_u32(&smBf[0][0]);

    // stage loader: 512 x 16B (hi at +0, lo at +4096 within each 8KB buffer)
    auto load_stage = [&](int i, int buf) {
        const uint32_t dst = smb + buf * 8192;
        cp_async16(dst + tid * 16,        (const uint4*)(g_Bf_hi + i * 1024) + tid);
        cp_async16(dst + 4096 + tid * 16, (const uint4*)(g_Bf_lo + i * 1024) + tid);
    };

    load_stage(ibase, 0);
    cp_commit();

    for (int t = 0; t < IPB; ++t) {
        if (t > 0) __syncthreads();          // prior compute done on next buffer
        if (t + 1 < IPB) {
            load_stage(ibase + t + 1, (t + 1) & 1);
            cp_commit();
            cp_wait<1>();
        } else {
            cp_wait<0>();
        }
        __syncthreads();                     // stage t visible

        const unsigned* bfh = &smBf[t & 1][0];
        const unsigned* bfl = &smBf[t & 1][1024];
        float* rowbase = out + ((size_t)(ibase + t) * LL + jt * 256 + w * 32) * PD;

        #pragma unroll 1
        for (int h = 0; h < 2; ++h) {        // nt halves: acc stays at 32 regs
            float acc[2][4][4];
            #pragma unroll
            for (int m = 0; m < 2; ++m)
                #pragma unroll
                for (int n4 = 0; n4 < 4; ++n4)
                    #pragma unroll
                    for (int e = 0; e < 4; ++e) acc[m][n4][e] = 0.f;

            #pragma unroll
            for (int n4 = 0; n4 < 4; ++n4) {
                const int nt = h * 4 + n4;
                uint4 H = *(const uint4*)(bfh + (nt * 32 + l) * 4);
                uint4 L = *(const uint4*)(bfl + (nt * 32 + l) * 4);
                uint2 Bh0 = make_uint2(H.x, H.y), Bh1 = make_uint2(H.z, H.w);
                uint2 Bl0 = make_uint2(L.x, L.y), Bl1 = make_uint2(L.z, L.w);
                #pragma unroll
                for (int m = 0; m < 2; ++m) {
                    MMA_BF16(acc[m][n4], Ah[0][m], Bh0);
                    MMA_BF16(acc[m][n4], Ah[0][m], Bl0);
                    MMA_BF16(acc[m][n4], Al[0][m], Bh0);
                    MMA_BF16(acc[m][n4], Ah[1][m], Bh1);
                    MMA_BF16(acc[m][n4], Ah[1][m], Bl1);
                    MMA_BF16(acc[m][n4], Al[1][m], Bh1);
                }
            }

            // epilogue half: bias via __ldg; 32B-sector float2 stores
            #pragma unroll
            for (int m = 0; m < 2; ++m)
                #pragma unroll
                for (int n4 = 0; n4 < 4; ++n4) {
                    const int nt = h * 4 + n4;
                    float2 bb = __ldg((const float2*)(b2 + nt * 8 + 2 * q));
                    float* d0 = rowbase + (m * 16 + gid) * PD + nt * 8 + 2 * q;
                    *(float2*)d0 =
                        make_float2(acc[m][n4][0] + bb.x, acc[m][n4][1] + bb.y);
                    *(float2*)(d0 + 8 * PD) =
                        make_float2(acc[m][n4][2] + bb.x, acc[m][n4][3] + bb.y);
                }
        }
    }
}

// ---------------------------------------------------------------------------
extern "C" void kernel_launch(void* const* d_in, const int* in_sizes, int n_in,
                              void* d_out, int out_size) {
    const float* seq = (const float*)d_in[0];
    const float* W1  = (const float*)d_in[1];
    const float* b1  = (const float*)d_in[2];
    const float* W2  = (const float*)d_in[3];
    const float* b2  = (const float*)d_in[4];
    float* out = (float*)d_out;

    k_proj1<<<128, 128>>>(seq, W1, b1);
    k_proj2<<<dim3(8, 16), 256>>>(W2);
    k_mma<<<dim3(2, LL / IPB), 256>>>(b2, out);
}

// round 12
// speedup vs baseline: 1.5873x; 1.0028x over previous
#include <cuda_runtime.h>
#include <cuda_bf16.h>
#include <cstdint>

#define LL 512
#define IN_DIM 256
#define DM 32      // dim_msa (contraction dims c and d)
#define PD 64      // pairwise dim
#define CP 2048    // DM*PD
#define IPB 4      // i's per CTA in k_mma

// ---------------------------------------------------------------------------
// Global scratch. Fragment layouts:
//   g_Af_*[ ((mt*2+ks)*32 + lane)*4 + reg ]            mt=j>>4 (32), ks=c>>4 (2)
//   g_Bf_*[ i*1024 + (nt*32 + lane)*4 + ks*2 + reg ]   nt=p>>3 (8)  <- 16B/(nt,lane)
// ---------------------------------------------------------------------------
__device__ __align__(16) unsigned g_Af_hi[8192];
__device__ __align__(16) unsigned g_Af_lo[8192];
__device__ __align__(16) unsigned g_Bf_hi[512 * 1024];
__device__ __align__(16) unsigned g_Bf_lo[512 * 1024];
__device__ float g_xT[DM * LL];          // x transposed: [d][i]

__device__ __forceinline__ unsigned pack_bf(__nv_bfloat16 lo16, __nv_bfloat16 hi16) {
    return (unsigned)__bfloat16_as_ushort(lo16) |
           ((unsigned)__bfloat16_as_ushort(hi16) << 16);
}
__device__ __forceinline__ void split_bf(float f, __nv_bfloat16& h, __nv_bfloat16& l) {
    h = __float2bfloat16(f);
    l = __float2bfloat16(f - __bfloat162float(h));
}
__device__ __forceinline__ uint32_t smem_u32(const void* p) {
    uint32_t a;
    asm("{ .reg .u64 t; cvta.to.shared.u64 t, %1; cvt.u32.u64 %0, t; }"
        : "=r"(a) : "l"(p));
    return a;
}
__device__ __forceinline__ void cp_async16(uint32_t dst, const void* src) {
    asm volatile("cp.async.cg.shared.global [%0], [%1], 16;"
                 :: "r"(dst), "l"(src) : "memory");
}
__device__ __forceinline__ void cp_commit() {
    asm volatile("cp.async.commit_group;" ::: "memory");
}
template <int N>
__device__ __forceinline__ void cp_wait() {
    asm volatile("cp.async.wait_group %0;" :: "n"(N) : "memory");
}

// ---------------------------------------------------------------------------
// Kernel A (R8, measured 5.9us): x = seq @ W1^T + b1; emits g_xT + A-frags.
// grid 128 x block 128; CTA = 4 rows; cross-warp reduce over k-chunks.
// ---------------------------------------------------------------------------
#define W1PAD 260
__global__ void __launch_bounds__(128) k_proj1(const float* __restrict__ seq,
                                               const float* __restrict__ W1,
                                               const float* __restrict__ b1) {
    __shared__ __align__(16) float W1s[DM][W1PAD];
    __shared__ __align__(16) float seqs[4][IN_DIM];
    __shared__ __align__(16) float red[4][4][32];
    const int tid = threadIdx.x;
    const int i0 = blockIdx.x * 4;

    #pragma unroll
    for (int t = 0; t < 16; ++t) {
        int idx4 = t * 128 + tid;
        int d = idx4 >> 6, k4 = idx4 & 63;
        *(float4*)&W1s[d][k4 * 4] = ((const float4*)W1)[idx4];
    }
    #pragma unroll
    for (int t = 0; t < 2; ++t) {
        int idx4 = t * 128 + tid;
        int r = idx4 >> 6, k4 = idx4 & 63;
        *(float4*)&seqs[r][k4 * 4] = ((const float4*)seq)[(i0 + r) * 64 + k4];
    }
    __syncthreads();

    const int d  = tid & 31;
    const int kc = tid >> 5;
    float acc[4][4];
    #pragma unroll
    for (int r = 0; r < 4; ++r)
        #pragma unroll
        for (int e = 0; e < 4; ++e) acc[r][e] = 0.f;

    #pragma unroll
    for (int i4 = 0; i4 < 16; ++i4) {
        float4 wv = *(const float4*)&W1s[d][kc * 64 + i4 * 4];
        #pragma unroll
        for (int r = 0; r < 4; ++r) {
            float4 s = *(const float4*)&seqs[r][kc * 64 + i4 * 4];
            acc[r][0] = fmaf(s.x, wv.x, acc[r][0]);
            acc[r][1] = fmaf(s.y, wv.y, acc[r][1]);
            acc[r][2] = fmaf(s.z, wv.z, acc[r][2]);
            acc[r][3] = fmaf(s.w, wv.w, acc[r][3]);
        }
    }
    #pragma unroll
    for (int r = 0; r < 4; ++r)
        red[r][kc][d] = (acc[r][0] + acc[r][1]) + (acc[r][2] + acc[r][3]);
    __syncthreads();

    const int rr = tid >> 5, dd = tid & 31;
    float a = (red[rr][0][dd] + red[rr][1][dd]) +
              (red[rr][2][dd] + red[rr][3][dd]) + b1[dd];

    const int j = i0 + rr;
    g_xT[dd * LL + j] = a;

    float pv = __shfl_xor_sync(0xffffffffu, a, 1);
    if (!(dd & 1)) {
        __nv_bfloat16 h0, l0, h1, l1;
        split_bf(a,  h0, l0);
        split_bf(pv, h1, l1);
        const int mt = j >> 4, jr = j & 15;
        const int ks = dd >> 4, kcx = dd & 15;
        const int lane = (jr & 7) * 4 + ((kcx >> 1) & 3);
        const int reg  = (jr >> 3) | ((kcx >> 3) << 1);
        const int idx  = ((mt * 2 + ks) * 32 + lane) * 4 + reg;
        g_Af_hi[idx] = pack_bf(h0, h1);
        g_Af_lo[idx] = pack_bf(l0, l1);
    }
}

// ---------------------------------------------------------------------------
// Kernel B: T = x @ W2-slice; emits B-fragments ONLY (new 16B layout).
// grid (8 cp-tiles, 16 i-tiles), block 256.
// ---------------------------------------------------------------------------
__global__ void __launch_bounds__(256) k_proj2(const float* __restrict__ W2) {
    __shared__ __align__(16) float ws[DM][256];
    __shared__ __align__(16) float xs[DM][32];
    const int tid = threadIdx.x;
    const int cp0 = blockIdx.x * 256;
    const int i0  = blockIdx.y * 32;

    #pragma unroll
    for (int t = 0; t < 32; ++t) {
        int idx = t * 256 + tid;
        int cpl = idx >> 5, k = idx & 31;
        int cp = cp0 + cpl;
        ws[k][cpl] = W2[(cp & 63) * 1024 + (cp >> 6) * 32 + k];
    }
    #pragma unroll
    for (int t = 0; t < 4; ++t) {
        int idx = t * 256 + tid;
        int k = idx >> 5, il = idx & 31;
        xs[k][il] = g_xT[k * LL + i0 + il];
    }
    __syncthreads();

    const int cg = tid & 31;
    const int ig = tid >> 5;
    float acc[4][8];
    #pragma unroll
    for (int a = 0; a < 4; ++a)
        #pragma unroll
        for (int b = 0; b < 8; ++b) acc[a][b] = 0.f;

    #pragma unroll 4
    for (int k = 0; k < DM; ++k) {
        float4 xv = *(const float4*)&xs[k][ig * 4];
        float4 wa = *(const float4*)&ws[k][cg * 8];
        float4 wb = *(const float4*)&ws[k][cg * 8 + 4];
        float xr[4] = {xv.x, xv.y, xv.z, xv.w};
        float wv[8] = {wa.x, wa.y, wa.z, wa.w, wb.x, wb.y, wb.z, wb.w};
        #pragma unroll
        for (int a = 0; a < 4; ++a)
            #pragma unroll
            for (int b = 0; b < 8; ++b)
                acc[a][b] = fmaf(xr[a], wv[b], acc[a][b]);
    }

    // B-fragment emit, new layout: (nt*32+lane)*4 + ks*2 + reg
    const int cbase = blockIdx.x * 4 + (cg >> 3);   // this thread's c
    const bool even = ((cg >> 3) & 1) == 0;
    const int nt = cg & 7;                           // p>>3
    #pragma unroll
    for (int a = 0; a < 4; ++a) {
        const int i = i0 + ig * 4 + a;
        unsigned* bh = g_Bf_hi + i * 1024;
        unsigned* bl = g_Bf_lo + i * 1024;
        #pragma unroll
        for (int b = 0; b < 8; ++b) {
            float v  = acc[a][b];
            float pv = __shfl_xor_sync(0xffffffffu, v, 8);
            if (even) {
                __nv_bfloat16 h0, l0, h1, l1;
                split_bf(v,  h0, l0);   // c (even)
                split_bf(pv, h1, l1);   // c+1
                const int ks = cbase >> 4, kc = cbase & 15;
                const int lanef = b * 4 + ((kc >> 1) & 3);
                const int reg   = kc >> 3;
                const int bidx  = (nt * 32 + lanef) * 4 + ks * 2 + reg;
                bh[bidx] = pack_bf(h0, h1);
                bl[bidx] = pack_bf(l0, l1);
            }
        }
    }
}

// ---------------------------------------------------------------------------
// Kernel C (pure HMMA): out[i][j][p] = b2[p] + sum_c x[j][c]*T[i][c][p]
// grid (2 jt, 128 ib), block 256 (8 warps x 32j x 64p), 2 CTAs/SM, IPB=4.
// B-frags: one LDS.128 per (nt, hi/lo). acc in nt-halves (32 regs live).
// ---------------------------------------------------------------------------
#define MMA_BF16(C, A, B)                                                      \
    asm volatile("mma.sync.aligned.m16n8k16.row.col.f32.bf16.bf16.f32 "        \
                 "{%0,%1,%2,%3}, {%4,%5,%6,%7}, {%8,%9}, {%0,%1,%2,%3};"       \
                 : "+f"((C)[0]), "+f"((C)[1]), "+f"((C)[2]), "+f"((C)[3])      \
                 : "r"((A).x), "r"((A).y), "r"((A).z), "r"((A).w),             \
                   "r"((B).x), "r"((B).y))

__global__ void __launch_bounds__(256, 2) k_mma(const float* __restrict__ b2,
                                                float* __restrict__ out) {
    __shared__ __align__(16) unsigned smBf[2][2048];   // [buf][hi 1024 | lo 1024]

    const int tid = threadIdx.x;
    const int w = tid >> 5, l = tid & 31;
    const int gid = l >> 2, q = l & 3;
    const int jt = blockIdx.x;
    const int ibase = blockIdx.y * IPB;

    // A fragments once per CTA (i-independent)
    uint4 Ah[2][2], Al[2][2];   // [ks][m]
    #pragma unroll
    for (int ks = 0; ks < 2; ++ks)
        #pragma unroll
        for (int m = 0; m < 2; ++m) {
            const int mt  = jt * 16 + w * 2 + m;
            const int off = ((mt * 2 + ks) * 32 + l) * 4;
            Ah[ks][m] = *(const uint4*)(g_Af_hi + off);
            Al[ks][m] = *(const uint4*)(g_Af_lo + off);
        }

    const uint32_t smb = smem_u32(&smBf[0][0]);

    // stage loader: 512 x 16B (hi at +0, lo at +4096 within each 8KB buffer)
    auto load_stage = [&](int i, int buf) {
        const uint32_t dst = smb + buf * 8192;
        cp_async16(dst + tid * 16,        (const uint4*)(g_Bf_hi + i * 1024) + tid);
        cp_async16(dst + 4096 + tid * 16, (const uint4*)(g_Bf_lo + i * 1024) + tid);
    };

    load_stage(ibase, 0);
    cp_commit();

    for (int t = 0; t < IPB; ++t) {
        if (t > 0) __syncthreads();          // prior compute done on next buffer
        if (t + 1 < IPB) {
            load_stage(ibase + t + 1, (t + 1) & 1);
            cp_commit();
            cp_wait<1>();
        } else {
            cp_wait<0>();
        }
        __syncthreads();                     // stage t visible

        const unsigned* bfh = &smBf[t & 1][0];
        const unsigned* bfl = &smBf[t & 1][1024];
        float* rowbase = out + ((size_t)(ibase + t) * LL + jt * 256 + w * 32) * PD;

        #pragma unroll 1
        for (int h = 0; h < 2; ++h) {        // nt halves: acc stays at 32 regs
            float acc[2][4][4];
            #pragma unroll
            for (int m = 0; m < 2; ++m)
                #pragma unroll
                for (int n4 = 0; n4 < 4; ++n4)
                    #pragma unroll
                    for (int e = 0; e < 4; ++e) acc[m][n4][e] = 0.f;

            #pragma unroll
            for (int n4 = 0; n4 < 4; ++n4) {
                const int nt = h * 4 + n4;
                uint4 H = *(const uint4*)(bfh + (nt * 32 + l) * 4);
                uint4 L = *(const uint4*)(bfl + (nt * 32 + l) * 4);
                uint2 Bh0 = make_uint2(H.x, H.y), Bh1 = make_uint2(H.z, H.w);
                uint2 Bl0 = make_uint2(L.x, L.y), Bl1 = make_uint2(L.z, L.w);
                #pragma unroll
                for (int m = 0; m < 2; ++m) {
                    MMA_BF16(acc[m][n4], Ah[0][m], Bh0);
                    MMA_BF16(acc[m][n4], Ah[0][m], Bl0);
                    MMA_BF16(acc[m][n4], Al[0][m], Bh0);
                    MMA_BF16(acc[m][n4], Ah[1][m], Bh1);
                    MMA_BF16(acc[m][n4], Ah[1][m], Bl1);
                    MMA_BF16(acc[m][n4], Al[1][m], Bh1);
                }
            }

            // epilogue half: bias via __ldg; 32B-sector float2 stores
            #pragma unroll
            for (int m = 0; m < 2; ++m)
                #pragma unroll
                for (int n4 = 0; n4 < 4; ++n4) {
                    const int nt = h * 4 + n4;
                    float2 bb = __ldg((const float2*)(b2 + nt * 8 + 2 * q));
                    float* d0 = rowbase + (m * 16 + gid) * PD + nt * 8 + 2 * q;
                    *(float2*)d0 =
                        make_float2(acc[m][n4][0] + bb.x, acc[m][n4][1] + bb.y);
                    *(float2*)(d0 + 8 * PD) =
                        make_float2(acc[m][n4][2] + bb.x, acc[m][n4][3] + bb.y);
                }
        }
    }
}

// ---------------------------------------------------------------------------
extern "C" void kernel_launch(void* const* d_in, const int* in_sizes, int n_in,
                              void* d_out, int out_size) {
    const float* seq = (const float*)d_in[0];
    const float* W1  = (const float*)d_in[1];
    const float* b1  = (const float*)d_in[2];
    const float* W2  = (const float*)d_in[3];
    const float* b2  = (const float*)d_in[4];
    float* out = (float*)d_out;

    k_proj1<<<128, 128>>>(seq, W1, b1);
    k_proj2<<<dim3(8, 16), 256>>>(W2);
    k_mma<<<dim3(2, LL / IPB), 256>>>(b2, out);
}

// round 13
// speedup vs baseline: 1.7990x; 1.1333x over previous
#include <cuda_runtime.h>
#include <cuda_fp16.h>
#include <cstdint>

#define LL 512
#define IN_DIM 256
#define DM 32      // dim_msa (contraction dims c and d)
#define PD 64      // pairwise dim
#define IPB 4      // i's per CTA in k_mma

// ---------------------------------------------------------------------------
// Global scratch. fp16 fragment layouts (single-term):
//   g_Af[ ((mt*2+ks)*32 + lane)*4 + reg ]            mt=j>>4 (32), ks=c>>4 (2)
//   g_Bf[ i*512 + (nt*32 + lane)*2... ] -> packed 16B/(nt,lane): (nt*32+lane)*4? 
//   g_Bf[ i*1024? ]  -- use (nt*32+lane)*4 + ks*2 + reg, 1024 u32/i? No: fp16
//   single-term B frag = 2 regs per ks -> 4 u32 per (nt,lane) = 1024 u32/i.
// ---------------------------------------------------------------------------
__device__ __align__(16) unsigned g_Af[8192];
__device__ __align__(16) unsigned g_Bf[512 * 1024];
__device__ float g_xT[DM * LL];          // x transposed: [d][i]

__device__ __forceinline__ unsigned pack_h2(float a, float b) {
    __half2 t = __floats2half2_rn(a, b);
    return *reinterpret_cast<unsigned*>(&t);
}
__device__ __forceinline__ uint32_t smem_u32(const void* p) {
    uint32_t a;
    asm("{ .reg .u64 t; cvta.to.shared.u64 t, %1; cvt.u32.u64 %0, t; }"
        : "=r"(a) : "l"(p));
    return a;
}
__device__ __forceinline__ void cp_async16(uint32_t dst, const void* src) {
    asm volatile("cp.async.cg.shared.global [%0], [%1], 16;"
                 :: "r"(dst), "l"(src) : "memory");
}
__device__ __forceinline__ void cp_commit() {
    asm volatile("cp.async.commit_group;" ::: "memory");
}
template <int N>
__device__ __forceinline__ void cp_wait() {
    asm volatile("cp.async.wait_group %0;" :: "n"(N) : "memory");
}

// ---------------------------------------------------------------------------
// Kernel A: x = seq @ W1^T + b1; emits g_xT + fp16 A-fragments.
// grid 128 x block 128; CTA = 4 rows; cross-warp reduce over k-chunks.
// ---------------------------------------------------------------------------
#define W1PAD 260
__global__ void __launch_bounds__(128) k_proj1(const float* __restrict__ seq,
                                               const float* __restrict__ W1,
                                               const float* __restrict__ b1) {
    __shared__ __align__(16) float W1s[DM][W1PAD];
    __shared__ __align__(16) float seqs[4][IN_DIM];
    __shared__ __align__(16) float red[4][4][32];
    const int tid = threadIdx.x;
    const int i0 = blockIdx.x * 4;

    #pragma unroll
    for (int t = 0; t < 16; ++t) {
        int idx4 = t * 128 + tid;
        int d = idx4 >> 6, k4 = idx4 & 63;
        *(float4*)&W1s[d][k4 * 4] = ((const float4*)W1)[idx4];
    }
    #pragma unroll
    for (int t = 0; t < 2; ++t) {
        int idx4 = t * 128 + tid;
        int r = idx4 >> 6, k4 = idx4 & 63;
        *(float4*)&seqs[r][k4 * 4] = ((const float4*)seq)[(i0 + r) * 64 + k4];
    }
    __syncthreads();

    const int d  = tid & 31;
    const int kc = tid >> 5;
    float acc[4][4];
    #pragma unroll
    for (int r = 0; r < 4; ++r)
        #pragma unroll
        for (int e = 0; e < 4; ++e) acc[r][e] = 0.f;

    #pragma unroll
    for (int i4 = 0; i4 < 16; ++i4) {
        float4 wv = *(const float4*)&W1s[d][kc * 64 + i4 * 4];
        #pragma unroll
        for (int r = 0; r < 4; ++r) {
            float4 s = *(const float4*)&seqs[r][kc * 64 + i4 * 4];
            acc[r][0] = fmaf(s.x, wv.x, acc[r][0]);
            acc[r][1] = fmaf(s.y, wv.y, acc[r][1]);
            acc[r][2] = fmaf(s.z, wv.z, acc[r][2]);
            acc[r][3] = fmaf(s.w, wv.w, acc[r][3]);
        }
    }
    #pragma unroll
    for (int r = 0; r < 4; ++r)
        red[r][kc][d] = (acc[r][0] + acc[r][1]) + (acc[r][2] + acc[r][3]);
    __syncthreads();

    const int rr = tid >> 5, dd = tid & 31;
    float a = (red[rr][0][dd] + red[rr][1][dd]) +
              (red[rr][2][dd] + red[rr][3][dd]) + b1[dd];

    const int j = i0 + rr;
    g_xT[dd * LL + j] = a;

    // A-fragment emit: pair (dd, dd^1) via shuffle; even lanes write packed fp16
    float pv = __shfl_xor_sync(0xffffffffu, a, 1);
    if (!(dd & 1)) {
        const int mt = j >> 4, jr = j & 15;
        const int ks = dd >> 4, kcx = dd & 15;
        const int lane = (jr & 7) * 4 + ((kcx >> 1) & 3);
        const int reg  = (jr >> 3) | ((kcx >> 3) << 1);
        const int idx  = ((mt * 2 + ks) * 32 + lane) * 4 + reg;
        g_Af[idx] = pack_h2(a, pv);
    }
}

// ---------------------------------------------------------------------------
// Kernel B: T = x @ W2-slice; emits fp16 B-fragments only.
// grid (8 cp-tiles, 16 i-tiles), block 256.
//   g_Bf[i*1024 + (nt*32+lane)*4 + ks*2 + reg]  -> 16B per (nt,lane)
// ---------------------------------------------------------------------------
__global__ void __launch_bounds__(256) k_proj2(const float* __restrict__ W2) {
    __shared__ __align__(16) float ws[DM][256];
    __shared__ __align__(16) float xs[DM][32];
    const int tid = threadIdx.x;
    const int cp0 = blockIdx.x * 256;
    const int i0  = blockIdx.y * 32;

    #pragma unroll
    for (int t = 0; t < 32; ++t) {
        int idx = t * 256 + tid;
        int cpl = idx >> 5, k = idx & 31;
        int cp = cp0 + cpl;
        ws[k][cpl] = W2[(cp & 63) * 1024 + (cp >> 6) * 32 + k];
    }
    #pragma unroll
    for (int t = 0; t < 4; ++t) {
        int idx = t * 256 + tid;
        int k = idx >> 5, il = idx & 31;
        xs[k][il] = g_xT[k * LL + i0 + il];
    }
    __syncthreads();

    const int cg = tid & 31;
    const int ig = tid >> 5;
    float acc[4][8];
    #pragma unroll
    for (int a = 0; a < 4; ++a)
        #pragma unroll
        for (int b = 0; b < 8; ++b) acc[a][b] = 0.f;

    #pragma unroll 4
    for (int k = 0; k < DM; ++k) {
        float4 xv = *(const float4*)&xs[k][ig * 4];
        float4 wa = *(const float4*)&ws[k][cg * 8];
        float4 wb = *(const float4*)&ws[k][cg * 8 + 4];
        float xr[4] = {xv.x, xv.y, xv.z, xv.w};
        float wv[8] = {wa.x, wa.y, wa.z, wa.w, wb.x, wb.y, wb.z, wb.w};
        #pragma unroll
        for (int a = 0; a < 4; ++a)
            #pragma unroll
            for (int b = 0; b < 8; ++b)
                acc[a][b] = fmaf(xr[a], wv[b], acc[a][b]);
    }

    // B-fragment emit: c = bx*4 + (cg>>3), p = (cg&7)*8 + b; partner lane
    // (cg^8) holds c^1 at same (i,p).
    const int cbase = blockIdx.x * 4 + (cg >> 3);
    const bool even = ((cg >> 3) & 1) == 0;
    const int nt = cg & 7;
    #pragma unroll
    for (int a = 0; a < 4; ++a) {
        const int i = i0 + ig * 4 + a;
        unsigned* bf = g_Bf + i * 1024;
        #pragma unroll
        for (int b = 0; b < 8; ++b) {
            float v  = acc[a][b];
            float pv = __shfl_xor_sync(0xffffffffu, v, 8);
            if (even) {
                const int ks = cbase >> 4, kc = cbase & 15;
                const int lanef = b * 4 + ((kc >> 1) & 3);
                const int reg   = kc >> 3;
                const int bidx  = (nt * 32 + lanef) * 4 + ks * 2 + reg;
                bf[bidx] = pack_h2(v, pv);
            }
        }
    }
}

// ---------------------------------------------------------------------------
// Kernel C (fp16 HMMA, single term): out[i][j][p] = b2[p] + sum_c x[j]x[i]W2
// grid (2 jt, 128 ib), block 256 (8 warps x 32j x 64p), 2 CTAs/SM, IPB=4.
// 32 MMAs/warp/i. Full 8-nt accumulator (64 regs).
// ---------------------------------------------------------------------------
#define MMA_F16(C, A, B)                                                       \
    asm volatile("mma.sync.aligned.m16n8k16.row.col.f32.f16.f16.f32 "          \
                 "{%0,%1,%2,%3}, {%4,%5,%6,%7}, {%8,%9}, {%0,%1,%2,%3};"       \
                 : "+f"((C)[0]), "+f"((C)[1]), "+f"((C)[2]), "+f"((C)[3])      \
                 : "r"((A).x), "r"((A).y), "r"((A).z), "r"((A).w),             \
                   "r"((B).x), "r"((B).y))

__global__ void __launch_bounds__(256, 2) k_mma(const float* __restrict__ b2,
                                                float* __restrict__ out) {
    __shared__ __align__(16) unsigned smBf[2][1024];   // [buf] 4 KB each

    const int tid = threadIdx.x;
    const int w = tid >> 5, l = tid & 31;
    const int gid = l >> 2, q = l & 3;
    const int jt = blockIdx.x;
    const int ibase = blockIdx.y * IPB;

    // A fragments once per CTA (i-independent): [ks][m]
    uint4 Af[2][2];
    #pragma unroll
    for (int ks = 0; ks < 2; ++ks)
        #pragma unroll
        for (int m = 0; m < 2; ++m) {
            const int mt  = jt * 16 + w * 2 + m;
            const int off = ((mt * 2 + ks) * 32 + l) * 4;
            Af[ks][m] = *(const uint4*)(g_Af + off);
        }

    const uint32_t smb = smem_u32(&smBf[0][0]);

    // stage loader: 256 x 16B per i
    auto load_stage = [&](int i, int buf) {
        cp_async16(smb + buf * 4096 + tid * 16,
                   (const uint4*)(g_Bf + i * 1024) + tid);
    };

    load_stage(ibase, 0);
    cp_commit();

    for (int t = 0; t < IPB; ++t) {
        if (t > 0) __syncthreads();          // prior compute done on next buffer
        if (t + 1 < IPB) {
            load_stage(ibase + t + 1, (t + 1) & 1);
            cp_commit();
            cp_wait<1>();
        } else {
            cp_wait<0>();
        }
        __syncthreads();                     // stage t visible

        const unsigned* bf = &smBf[t & 1][0];
        float* rowbase = out + ((size_t)(ibase + t) * LL + jt * 256 + w * 32) * PD;

        float acc[2][8][4];
        #pragma unroll
        for (int m = 0; m < 2; ++m)
            #pragma unroll
            for (int n = 0; n < 8; ++n)
                #pragma unroll
                for (int e = 0; e < 4; ++e) acc[m][n][e] = 0.f;

        #pragma unroll
        for (int n = 0; n < 8; ++n) {
            uint4 B = *(const uint4*)(bf + (n * 32 + l) * 4);
            uint2 B0 = make_uint2(B.x, B.y);   // ks=0
            uint2 B1 = make_uint2(B.z, B.w);   // ks=1
            #pragma unroll
            for (int m = 0; m < 2; ++m) {
                MMA_F16(acc[m][n], Af[0][m], B0);
                MMA_F16(acc[m][n], Af[1][m], B1);
            }
        }

        // epilogue: bias via __ldg; 32B-sector float2 stores
        #pragma unroll
        for (int m = 0; m < 2; ++m)
            #pragma unroll
            for (int n = 0; n < 8; ++n) {
                float2 bb = __ldg((const float2*)(b2 + n * 8 + 2 * q));
                float* d0 = rowbase + (m * 16 + gid) * PD + n * 8 + 2 * q;
                *(float2*)d0 =
                    make_float2(acc[m][n][0] + bb.x, acc[m][n][1] + bb.y);
                *(float2*)(d0 + 8 * PD) =
                    make_float2(acc[m][n][2] + bb.x, acc[m][n][3] + bb.y);
            }
    }
}

// ---------------------------------------------------------------------------
extern "C" void kernel_launch(void* const* d_in, const int* in_sizes, int n_in,
                              void* d_out, int out_size) {
    const float* seq = (const float*)d_in[0];
    const float* W1  = (const float*)d_in[1];
    const float* b1  = (const float*)d_in[2];
    const float* W2  = (const float*)d_in[3];
    const float* b2  = (const float*)d_in[4];
    float* out = (float*)d_out;

    k_proj1<<<128, 128>>>(seq, W1, b1);
    k_proj2<<<dim3(8, 16), 256>>>(W2);
    k_mma<<<dim3(2, LL / IPB), 256>>>(b2, out);
}